// round 6
// baseline (speedup 1.0000x reference)
#include <cuda_runtime.h>

// Vanilla tanh RNN: B=4096, T=2048, I=4, H=20, O=4.
// Warp-synchronous, h via warp-private SMEM ping-pong + one __syncwarp/step,
// f32x2 dot packed over j, single-MUFU tanh.approx, 8-deep x prefetch ring.
// R6 change: 2 batches/warp (20 live lanes) x 14 warps/CTA -> 3.5 warps/SMSP
// for latency coverage (uniform partition; 2048 active warps, no clamping).

#define B_TOTAL 4096
#define T_STEPS 2048
#define H_DIM   20
#define O_DIM   4
#define WARPS_CTA 14
#define CTA_THREADS (WARPS_CTA * 32)
#define GRID 148
#define PF 8                       // x prefetch depth (steps)

typedef unsigned long long u64;

__device__ __forceinline__ u64 pack2(float lo, float hi) {
    u64 r; asm("mov.b64 %0, {%1,%2};" : "=l"(r) : "f"(lo), "f"(hi)); return r;
}
__device__ __forceinline__ void unpack2(u64 v, float& lo, float& hi) {
    asm("mov.b64 {%0,%1}, %2;" : "=f"(lo), "=f"(hi) : "l"(v));
}
__device__ __forceinline__ u64 fma2(u64 a, u64 b, u64 c) {
    u64 d; asm("fma.rn.f32x2 %0, %1, %2, %3;" : "=l"(d) : "l"(a), "l"(b), "l"(c)); return d;
}
__device__ __forceinline__ u64 add2(u64 a, u64 b) {
    u64 d; asm("add.rn.f32x2 %0, %1, %2;" : "=l"(d) : "l"(a), "l"(b)); return d;
}
__device__ __forceinline__ float tanha(float x) {
    float r; asm("tanh.approx.f32 %0, %1;" : "=f"(r) : "f"(x)); return r;
}

__device__ __forceinline__ void rnn_step(
    const float* __restrict__ src, float* __restrict__ dst,
    int g, int o0, bool st, ulonglong2 xv,
    const u64* __restrict__ W0, const u64* __restrict__ W1,
    ulonglong2 Wi0, ulonglong2 Wi1, u64 seed0, u64 seed1)
{
    const ulonglong2* hsrc = reinterpret_cast<const ulonglong2*>(src + g * H_DIM);
    ulonglong2 hv0 = hsrc[0];
    ulonglong2 hv1 = hsrc[1];
    ulonglong2 hv2 = hsrc[2];
    ulonglong2 hv3 = hsrc[3];
    ulonglong2 hv4 = hsrc[4];

    // 4 independent f32x2 chains (2 per output); x/bias seeding is h-independent
    // and overlaps the LDS latency.
    u64 a0 = fma2(xv.x, Wi0.x, seed0);
    u64 b0 = fma2(xv.y, Wi0.y, pack2(0.f, 0.f));
    u64 a1 = fma2(xv.x, Wi1.x, seed1);
    u64 b1 = fma2(xv.y, Wi1.y, pack2(0.f, 0.f));

    a0 = fma2(hv0.x, W0[0], a0);  b0 = fma2(hv0.y, W0[1], b0);
    a1 = fma2(hv0.x, W1[0], a1);  b1 = fma2(hv0.y, W1[1], b1);
    a0 = fma2(hv1.x, W0[2], a0);  b0 = fma2(hv1.y, W0[3], b0);
    a1 = fma2(hv1.x, W1[2], a1);  b1 = fma2(hv1.y, W1[3], b1);
    a0 = fma2(hv2.x, W0[4], a0);  b0 = fma2(hv2.y, W0[5], b0);
    a1 = fma2(hv2.x, W1[4], a1);  b1 = fma2(hv2.y, W1[5], b1);
    a0 = fma2(hv3.x, W0[6], a0);  b0 = fma2(hv3.y, W0[7], b0);
    a1 = fma2(hv3.x, W1[6], a1);  b1 = fma2(hv3.y, W1[7], b1);
    a0 = fma2(hv4.x, W0[8], a0);  b0 = fma2(hv4.y, W0[9], b0);
    a1 = fma2(hv4.x, W1[8], a1);  b1 = fma2(hv4.y, W1[9], b1);

    u64 s0 = add2(a0, b0);
    u64 s1 = add2(a1, b1);

    float l0, h0f, l1, h1f;
    unpack2(s0, l0, h0f);
    unpack2(s1, l1, h1f);
    float t0 = tanha(l0 + h0f);
    float t1 = tanha(l1 + h1f);

    if (st) {
        *reinterpret_cast<u64*>(dst + g * H_DIM + o0) = pack2(t0, t1);
    }
    __syncwarp();
}

__global__ void __launch_bounds__(CTA_THREADS, 1)
rnn_tanh_kernel(
    const float* __restrict__ x,     const float* __restrict__ h0,
    const float* __restrict__ W_ih,  const float* __restrict__ W_hh,
    const float* __restrict__ b_ih,  const float* __restrict__ b_hh,
    const float* __restrict__ fc_w,  const float* __restrict__ fc_b,
    float* __restrict__ out)
{
    __shared__ __align__(128) float sm[WARPS_CTA][2][64];

    const int lane = threadIdx.x & 31;
    const int w    = threadIdx.x >> 5;
    const int gw   = blockIdx.x * WARPS_CTA + w;     // global warp id
    if (gw * 2 >= B_TOTAL) return;                   // whole warp idle (24 warps)

    const int  g  = (lane < 20) ? (lane / 10) : 1;   // batch within warp (clamped)
    const int  p  = lane % 10;                       // output pair within batch
    const bool st = (lane < 20);                     // this lane is live
    const int  b  = gw * 2 + g;                      // always < B_TOTAL
    const int  o0 = 2 * p;                           // owned outputs o0, o0+1

    // ---- per-thread weights (packed over j) ----
    const u64* whh = reinterpret_cast<const u64*>(W_hh);   // row = 10 u64 pairs
    u64 W0[10], W1[10];
    #pragma unroll
    for (int q = 0; q < 10; q++) {
        W0[q] = __ldg(&whh[o0 * 10 + q]);
        W1[q] = __ldg(&whh[(o0 + 1) * 10 + q]);
    }
    const ulonglong2* wih = reinterpret_cast<const ulonglong2*>(W_ih);  // row = 16B
    ulonglong2 Wi0 = __ldg(&wih[o0]);
    ulonglong2 Wi1 = __ldg(&wih[o0 + 1]);
    const float bias0 = __ldg(&b_ih[o0])     + __ldg(&b_hh[o0]);
    const float bias1 = __ldg(&b_ih[o0 + 1]) + __ldg(&b_hh[o0 + 1]);
    const u64 seed0 = pack2(bias0, 0.f);
    const u64 seed1 = pack2(bias1, 0.f);

    float* bufA = &sm[w][0][0];
    float* bufB = &sm[w][1][0];

    // ---- init h (plain layout) into buffer A ----
    {
        const float2* h2 = reinterpret_cast<const float2*>(h0);
        float2 hv = __ldg(&h2[b * (H_DIM / 2) + p]);
        if (st) *reinterpret_cast<u64*>(bufA + g * H_DIM + o0) = pack2(hv.x, hv.y);
    }
    __syncwarp();

    // x[b][t] is 4 floats = one ulonglong2. 8-deep register prefetch ring.
    const ulonglong2* xp = reinterpret_cast<const ulonglong2*>(x) + (size_t)b * T_STEPS;
    ulonglong2 xbuf[PF];
    #pragma unroll
    for (int q = 0; q < PF; q++) xbuf[q] = __ldg(&xp[q]);

    for (int t = 0; t < T_STEPS; t += PF) {
        #pragma unroll
        for (int q = 0; q < PF; q++) {
            ulonglong2 xv = xbuf[q];
            int nidx = t + q + PF;
            xbuf[q] = __ldg(&xp[(nidx < T_STEPS) ? nidx : (T_STEPS - 1)]);
            if (q & 1)
                rnn_step(bufB, bufA, g, o0, st, xv, W0, W1, Wi0, Wi1, seed0, seed1);
            else
                rnn_step(bufA, bufB, g, o0, st, xv, W0, W1, Wi0, Wi1, seed0, seed1);
        }
    }

    // Final h is in bufA (T_STEPS multiple of PF, even). Linear head: lanes p < 4.
    if (st && p < O_DIM) {
        const float* hf = bufA + g * H_DIM;
        float acc = __ldg(&fc_b[p]);
        #pragma unroll
        for (int j = 0; j < H_DIM; j++)
            acc = fmaf(hf[j], __ldg(&fc_w[p * H_DIM + j]), acc);
        out[b * O_DIM + p] = acc;
    }
}

extern "C" void kernel_launch(void* const* d_in, const int* in_sizes, int n_in,
                              void* d_out, int out_size)
{
    const float* x    = (const float*)d_in[0];
    const float* h0   = (const float*)d_in[1];
    const float* W_ih = (const float*)d_in[2];
    const float* W_hh = (const float*)d_in[3];
    const float* b_ih = (const float*)d_in[4];
    const float* b_hh = (const float*)d_in[5];
    const float* fc_w = (const float*)d_in[6];
    const float* fc_b = (const float*)d_in[7];
    float* out = (float*)d_out;

    rnn_tanh_kernel<<<GRID, CTA_THREADS>>>(x, h0, W_ih, W_hh, b_ih, b_hh,
                                           fc_w, fc_b, out);
}

// round 7
// speedup vs baseline: 1.3240x; 1.3240x over previous
#include <cuda_runtime.h>

// Vanilla tanh RNN: B=4096, T=2048, I=4, H=20, O=4.
// R5 skeleton (best: 10 warps/CTA, 3 batches/warp, 30/32 lanes live, f32x2 dot,
// tanh.approx, 8-deep x prefetch ring).
// R7: (a) no per-step __syncwarp -- loop body is branch-free/unconditional so the
// warp stays converged and per-warp in-order smem gives STS->LDS ordering;
// (b) unconditional stores (lanes 30/31 -> scratch words 60/62);
// (c) clamp-free prefetch with an epilogue, removing per-step SEL/min.

#define B_TOTAL 4096
#define T_STEPS 2048
#define H_DIM   20
#define O_DIM   4
#define WARPS_CTA 10
#define CTA_THREADS (WARPS_CTA * 32)
#define GRID 148
#define PF 8                       // x prefetch depth (steps)

typedef unsigned long long u64;

__device__ __forceinline__ u64 pack2(float lo, float hi) {
    u64 r; asm("mov.b64 %0, {%1,%2};" : "=l"(r) : "f"(lo), "f"(hi)); return r;
}
__device__ __forceinline__ void unpack2(u64 v, float& lo, float& hi) {
    asm("mov.b64 {%0,%1}, %2;" : "=f"(lo), "=f"(hi) : "l"(v));
}
__device__ __forceinline__ u64 fma2(u64 a, u64 b, u64 c) {
    u64 d; asm("fma.rn.f32x2 %0, %1, %2, %3;" : "=l"(d) : "l"(a), "l"(b), "l"(c)); return d;
}
__device__ __forceinline__ u64 add2(u64 a, u64 b) {
    u64 d; asm("add.rn.f32x2 %0, %1, %2;" : "=l"(d) : "l"(a), "l"(b)); return d;
}
__device__ __forceinline__ float tanha(float x) {
    float r; asm("tanh.approx.f32 %0, %1;" : "=f"(r) : "f"(x)); return r;
}

// One RNN step. Branch-free, unconditional store (sOff routes dead lanes to scratch).
__device__ __forceinline__ void rnn_step(
    const float* __restrict__ src, float* __restrict__ dst,
    int gld, int sOff, ulonglong2 xv,
    const u64* __restrict__ W0, const u64* __restrict__ W1,
    ulonglong2 Wi0, ulonglong2 Wi1, u64 seed0, u64 seed1)
{
    const ulonglong2* hsrc = reinterpret_cast<const ulonglong2*>(src + gld * H_DIM);
    ulonglong2 hv0 = hsrc[0];
    ulonglong2 hv1 = hsrc[1];
    ulonglong2 hv2 = hsrc[2];
    ulonglong2 hv3 = hsrc[3];
    ulonglong2 hv4 = hsrc[4];

    // 4 independent f32x2 chains (2 per output); x/bias seeds overlap LDS latency.
    u64 a0 = fma2(xv.x, Wi0.x, seed0);
    u64 b0 = fma2(xv.y, Wi0.y, pack2(0.f, 0.f));
    u64 a1 = fma2(xv.x, Wi1.x, seed1);
    u64 b1 = fma2(xv.y, Wi1.y, pack2(0.f, 0.f));

    a0 = fma2(hv0.x, W0[0], a0);  b0 = fma2(hv0.y, W0[1], b0);
    a1 = fma2(hv0.x, W1[0], a1);  b1 = fma2(hv0.y, W1[1], b1);
    a0 = fma2(hv1.x, W0[2], a0);  b0 = fma2(hv1.y, W0[3], b0);
    a1 = fma2(hv1.x, W1[2], a1);  b1 = fma2(hv1.y, W1[3], b1);
    a0 = fma2(hv2.x, W0[4], a0);  b0 = fma2(hv2.y, W0[5], b0);
    a1 = fma2(hv2.x, W1[4], a1);  b1 = fma2(hv2.y, W1[5], b1);
    a0 = fma2(hv3.x, W0[6], a0);  b0 = fma2(hv3.y, W0[7], b0);
    a1 = fma2(hv3.x, W1[6], a1);  b1 = fma2(hv3.y, W1[7], b1);
    a0 = fma2(hv4.x, W0[8], a0);  b0 = fma2(hv4.y, W0[9], b0);
    a1 = fma2(hv4.x, W1[8], a1);  b1 = fma2(hv4.y, W1[9], b1);

    u64 s0 = add2(a0, b0);
    u64 s1 = add2(a1, b1);

    float l0, h0f, l1, h1f;
    unpack2(s0, l0, h0f);
    unpack2(s1, l1, h1f);
    float t0 = tanha(l0 + h0f);
    float t1 = tanha(l1 + h1f);

    *reinterpret_cast<u64*>(dst + sOff) = pack2(t0, t1);   // unconditional
    asm volatile("" ::: "memory");   // pin program order of smem ops
}

__global__ void __launch_bounds__(CTA_THREADS, 1)
rnn_tanh_kernel(
    const float* __restrict__ x,     const float* __restrict__ h0,
    const float* __restrict__ W_ih,  const float* __restrict__ W_hh,
    const float* __restrict__ b_ih,  const float* __restrict__ b_hh,
    const float* __restrict__ fc_w,  const float* __restrict__ fc_b,
    float* __restrict__ out)
{
    __shared__ __align__(128) float sm[WARPS_CTA][2][64];

    const int lane = threadIdx.x & 31;
    const int w    = threadIdx.x >> 5;
    const int gw   = blockIdx.x * WARPS_CTA + w;     // global warp id
    if (gw * 3 >= B_TOTAL) return;                   // whole warp idle

    const bool live = (lane < 30);
    const int  g    = live ? (lane / 10) : 2;        // batch (reads clamped)
    const int  p    = live ? (lane % 10) : (lane - 30);
    const int  b    = gw * 3 + g;
    const int  bc   = (b < B_TOTAL) ? b : (B_TOTAL - 1);
    const int  o0   = 2 * p;                         // owned outputs o0, o0+1
    // store offset: live lanes -> real slot; lanes 30/31 -> scratch words 60/62
    const int  sOff = live ? (g * H_DIM + o0) : (60 + (lane - 30) * 2);

    // ---- per-thread weights (packed over j) ----
    const u64* whh = reinterpret_cast<const u64*>(W_hh);   // row = 10 u64 pairs
    u64 W0[10], W1[10];
    #pragma unroll
    for (int q = 0; q < 10; q++) {
        W0[q] = __ldg(&whh[o0 * 10 + q]);
        W1[q] = __ldg(&whh[(o0 + 1) * 10 + q]);
    }
    const ulonglong2* wih = reinterpret_cast<const ulonglong2*>(W_ih);  // row = 16B
    ulonglong2 Wi0 = __ldg(&wih[o0]);
    ulonglong2 Wi1 = __ldg(&wih[o0 + 1]);
    const float bias0 = __ldg(&b_ih[o0])     + __ldg(&b_hh[o0]);
    const float bias1 = __ldg(&b_ih[o0 + 1]) + __ldg(&b_hh[o0 + 1]);
    const u64 seed0 = pack2(bias0, 0.f);
    const u64 seed1 = pack2(bias1, 0.f);

    float* bufA = &sm[w][0][0];
    float* bufB = &sm[w][1][0];

    // ---- init h (plain layout) into buffer A ----
    {
        const float2* h2 = reinterpret_cast<const float2*>(h0);
        float2 hv = __ldg(&h2[bc * (H_DIM / 2) + p]);
        *reinterpret_cast<u64*>(bufA + sOff) = pack2(hv.x, hv.y);
    }
    __syncwarp();

    // x[b][t] = 4 floats = one ulonglong2. 8-deep register prefetch ring.
    const ulonglong2* xp = reinterpret_cast<const ulonglong2*>(x) + (size_t)bc * T_STEPS;
    ulonglong2 xbuf[PF];
    #pragma unroll
    for (int q = 0; q < PF; q++) xbuf[q] = __ldg(&xp[q]);

    // Main loop: prefetch unclamped (t+q+PF <= T-1 for t <= T-2*PF).
    for (int t = 0; t < T_STEPS - PF; t += PF) {
        #pragma unroll
        for (int q = 0; q < PF; q++) {
            ulonglong2 xv = xbuf[q];
            xbuf[q] = __ldg(&xp[t + q + PF]);
            if (q & 1)
                rnn_step(bufB, bufA, g, sOff, xv, W0, W1, Wi0, Wi1, seed0, seed1);
            else
                rnn_step(bufA, bufB, g, sOff, xv, W0, W1, Wi0, Wi1, seed0, seed1);
        }
    }
    // Epilogue: last PF steps, no prefetch.
    #pragma unroll
    for (int q = 0; q < PF; q++) {
        if (q & 1)
            rnn_step(bufB, bufA, g, sOff, xbuf[q], W0, W1, Wi0, Wi1, seed0, seed1);
        else
            rnn_step(bufA, bufB, g, sOff, xbuf[q], W0, W1, Wi0, Wi1, seed0, seed1);
    }

    // Final h is in bufA (T_STEPS even). Linear head: live lanes with p < 4.
    __syncwarp();
    if (live && p < O_DIM && b < B_TOTAL) {
        const float* hf = bufA + g * H_DIM;
        float acc = __ldg(&fc_b[p]);
        #pragma unroll
        for (int j = 0; j < H_DIM; j++)
            acc = fmaf(hf[j], __ldg(&fc_w[p * H_DIM + j]), acc);
        out[b * O_DIM + p] = acc;
    }
}

extern "C" void kernel_launch(void* const* d_in, const int* in_sizes, int n_in,
                              void* d_out, int out_size)
{
    const float* x    = (const float*)d_in[0];
    const float* h0   = (const float*)d_in[1];
    const float* W_ih = (const float*)d_in[2];
    const float* W_hh = (const float*)d_in[3];
    const float* b_ih = (const float*)d_in[4];
    const float* b_hh = (const float*)d_in[5];
    const float* fc_w = (const float*)d_in[6];
    const float* fc_b = (const float*)d_in[7];
    float* out = (float*)d_out;

    rnn_tanh_kernel<<<GRID, CTA_THREADS>>>(x, h0, W_ih, W_hh, b_ih, b_hh,
                                           fc_w, fc_b, out);
}